// round 1
// baseline (speedup 1.0000x reference)
#include <cuda_runtime.h>
#include <cstdint>

// CutStripes: out[b,c,t,f] = mask(b,t) ? x[perm[b],c,t,f] : x[b,c,t,f]
// Shapes: x (128,1,2048,128) f32; perm (128) i32; bgn,distance (128,4) i32.
// mask(b,t) = any_s( bgn[b,s] <= t < bgn[b,s]+distance[b,s] )
//
// Pure HBM-streaming kernel: one float4 per thread, one warp per (b,t) row
// so the mask test + perm load are warp-uniform broadcasts.
// T*F4 = 2048*32 = 65536 = 2^16 -> pure shift/mask indexing.

static constexpr int B  = 128;
static constexpr int T  = 2048;
static constexpr int F4 = 32;               // 128 floats / 4
static constexpr long TOTAL4 = (long)B * T * F4;   // 8,388,608 float4

__global__ void __launch_bounds__(256, 8)
cutstripes_kernel(const float4* __restrict__ x,
                  const int*    __restrict__ perm,
                  const int*    __restrict__ bgn,
                  const int*    __restrict__ dist,
                  float4*       __restrict__ out)
{
    const unsigned idx = blockIdx.x * 256u + threadIdx.x;   // < 2^23, fits u32
    const int t = (idx >> 5) & (T - 1);
    const int b = idx >> 16;

    // 2 x 128-bit loads of the 4 stripe params (warp-uniform, L1-hit)
    const int4 bg = __ldg((const int4*)(bgn  + (b << 2)));
    const int4 ds = __ldg((const int4*)(dist + (b << 2)));

    const bool m = ((unsigned)(t - bg.x) < (unsigned)ds.x) |
                   ((unsigned)(t - bg.y) < (unsigned)ds.y) |
                   ((unsigned)(t - bg.z) < (unsigned)ds.z) |
                   ((unsigned)(t - bg.w) < (unsigned)ds.w);

    const int src_b = m ? __ldg(perm + b) : b;

    // src offset = src_b * 2^16 + (t*32 + f4) = (src_b<<16) | (idx & 0xFFFF)
    out[idx] = x[((unsigned)src_b << 16) | (idx & 0xFFFFu)];
}

extern "C" void kernel_launch(void* const* d_in, const int* in_sizes, int n_in,
                              void* d_out, int out_size)
{
    const float4* x    = (const float4*)d_in[0];
    const int*    perm = (const int*)   d_in[1];
    const int*    bgn  = (const int*)   d_in[2];
    const int*    dist = (const int*)   d_in[3];
    float4*       out  = (float4*)      d_out;

    const int threads = 256;
    const int blocks  = (int)(TOTAL4 / threads);   // 32768
    cutstripes_kernel<<<blocks, threads>>>(x, perm, bgn, dist, out);
}

// round 2
// speedup vs baseline: 1.1356x; 1.1356x over previous
#include <cuda_runtime.h>
#include <cstdint>

// CutStripes: out[b,c,t,f] = mask(b,t) ? x[perm[b],c,t,f] : x[b,c,t,f]
// x (128,1,2048,128) f32; perm (128) i32; bgn,distance (128,4) i32.
//
// HBM-streaming kernel, MLP=4 per thread: each thread owns 4 float4 at
// stride 256 within a 1024-float4 block slab. All 4 loads are issued
// before any store (front-batched -> 4 outstanding 128B loads/thread).
// A 1024-float4 slab is fully inside one batch b (65536 float4 per b,
// aligned), so stripe params + perm are block-uniform.

static constexpr int T  = 2048;
static constexpr long TOTAL4 = 128L * 2048L * 32L;   // 8,388,608 float4
static constexpr int ITEMS = 4;
static constexpr int THREADS = 256;

__global__ void __launch_bounds__(THREADS)
cutstripes_kernel(const float4* __restrict__ x,
                  const int*    __restrict__ perm,
                  const int*    __restrict__ bgn,
                  const int*    __restrict__ dist,
                  float4*       __restrict__ out)
{
    // Block slab: 1024 consecutive float4. b uniform across the block.
    const unsigned base = blockIdx.x * (THREADS * ITEMS) + threadIdx.x;
    const int b = blockIdx.x >> 6;                 // (blk*1024) >> 16

    // Block-uniform stripe params + permuted batch (L1-resident).
    const int4 bg = __ldg((const int4*)(bgn  + (b << 2)));
    const int4 ds = __ldg((const int4*)(dist + (b << 2)));
    const int  pb = __ldg(perm + b);

    unsigned idx[ITEMS];
    unsigned src[ITEMS];
#pragma unroll
    for (int k = 0; k < ITEMS; k++) {
        idx[k] = base + k * THREADS;
        const int t = (idx[k] >> 5) & (T - 1);
        const bool m = ((unsigned)(t - bg.x) < (unsigned)ds.x) |
                       ((unsigned)(t - bg.y) < (unsigned)ds.y) |
                       ((unsigned)(t - bg.z) < (unsigned)ds.z) |
                       ((unsigned)(t - bg.w) < (unsigned)ds.w);
        const int src_b = m ? pb : b;
        src[k] = ((unsigned)src_b << 16) | (idx[k] & 0xFFFFu);
    }

    // Front-batched loads: 4 outstanding 128B LDGs per thread.
    float4 v[ITEMS];
#pragma unroll
    for (int k = 0; k < ITEMS; k++)
        v[k] = __ldcs(x + src[k]);          // streaming: no reuse

#pragma unroll
    for (int k = 0; k < ITEMS; k++)
        __stcs(out + idx[k], v[k]);         // streaming store

}

extern "C" void kernel_launch(void* const* d_in, const int* in_sizes, int n_in,
                              void* d_out, int out_size)
{
    const float4* x    = (const float4*)d_in[0];
    const int*    perm = (const int*)   d_in[1];
    const int*    bgn  = (const int*)   d_in[2];
    const int*    dist = (const int*)   d_in[3];
    float4*       out  = (float4*)      d_out;

    const int blocks = (int)(TOTAL4 / (THREADS * ITEMS));   // 8192
    cutstripes_kernel<<<blocks, THREADS>>>(x, perm, bgn, dist, out);
}